// round 8
// baseline (speedup 1.0000x reference)
#include <cuda_runtime.h>
#include <cuda_bf16.h>
#include <cstdint>
#include <math.h>

#define B_DIM 32
#define Q_DIM 32
#define P_DIM 196
#define D_DIM 1024
#define MROWS (B_DIM*Q_DIM)        // 1024
#define NCOLS (B_DIM*P_DIM)        // 6272
#define N4    (MROWS*NCOLS)

// ---------------- scratch ----------------
__device__ __nv_bfloat16 g_tn[MROWS * D_DIM];
__device__ __nv_bfloat16 g_vn[NCOLS * D_DIM];
__device__ float         g_sim[(size_t)MROWS * NCOLS];

// ---------------- kernel 1: warp-per-row L2 normalize + f32->bf16 ----------------
__global__ __launch_bounds__(256) void normalize_kernel(const float* __restrict__ tf,
                                                        const float* __restrict__ vf)
{
    const int w = blockIdx.x * 8 + (threadIdx.x >> 5);   // global row id (0..7295)
    const int lane = threadIdx.x & 31;
    const float* in;
    __nv_bfloat16* out;
    int row;
    if (w < MROWS) { in = tf; out = g_tn; row = w; }
    else           { in = vf; out = g_vn; row = w - MROWS; }

    const float4* src = reinterpret_cast<const float4*>(in + (size_t)row * D_DIM);
    float4 v[8];
    float ss = 0.f;
    #pragma unroll
    for (int i = 0; i < 8; i++) {
        v[i] = src[i * 32 + lane];
        ss += v[i].x*v[i].x + v[i].y*v[i].y + v[i].z*v[i].z + v[i].w*v[i].w;
    }
    #pragma unroll
    for (int o = 16; o; o >>= 1) ss += __shfl_xor_sync(0xffffffffu, ss, o);
    const float s = 1.0f / fmaxf(sqrtf(ss), 1e-8f);

    uint2* dst = reinterpret_cast<uint2*>(out + (size_t)row * D_DIM);
    #pragma unroll
    for (int i = 0; i < 8; i++) {
        __nv_bfloat162 h0 = __floats2bfloat162_rn(v[i].x * s, v[i].y * s);
        __nv_bfloat162 h1 = __floats2bfloat162_rn(v[i].z * s, v[i].w * s);
        uint2 u;
        u.x = *reinterpret_cast<uint32_t*>(&h0);
        u.y = *reinterpret_cast<uint32_t*>(&h1);
        dst[i * 32 + lane] = u;
    }
}

// ---------------- kernel 2: bf16 tensor-core GEMM  C[M,N] = A[M,K] * B[N,K]^T ----------------
__device__ __forceinline__ void cp_async16(uint32_t dst, const void* src) {
    asm volatile("cp.async.cg.shared.global [%0], [%1], 16;\n" :: "r"(dst), "l"(src));
}
__device__ __forceinline__ void ldsm_x4(uint32_t* r, uint32_t addr) {
    asm volatile("ldmatrix.sync.aligned.m8n8.x4.shared.b16 {%0,%1,%2,%3}, [%4];\n"
                 : "=r"(r[0]), "=r"(r[1]), "=r"(r[2]), "=r"(r[3]) : "r"(addr));
}
__device__ __forceinline__ void mma16816(float* c, const uint32_t* a, const uint32_t* b) {
    asm volatile("mma.sync.aligned.m16n8k16.row.col.f32.bf16.bf16.f32 "
                 "{%0,%1,%2,%3}, {%4,%5,%6,%7}, {%8,%9}, {%0,%1,%2,%3};\n"
                 : "+f"(c[0]), "+f"(c[1]), "+f"(c[2]), "+f"(c[3])
                 : "r"(a[0]), "r"(a[1]), "r"(a[2]), "r"(a[3]), "r"(b[0]), "r"(b[1]));
}

#define SSTR    40                        // padded bf16 stride (80B/row)
#define STAGES  4
#define AB_HALF (128 * SSTR)              // bf16 elems per A (or B) stage = 5120
#define STAGE_E (2 * AB_HALF)             // elems per stage (A then B)
#define GM_SMEM (STAGES * STAGE_E * 2)    // bytes = 81920

extern __shared__ __nv_bfloat16 gsm[];

__global__ __launch_bounds__(256, 2) void gemm_kernel()
{
    const __nv_bfloat16* __restrict__ A  = g_tn;
    const __nv_bfloat16* __restrict__ Bm = g_vn;

    const int tid  = threadIdx.x;
    const int lane = tid & 31;
    const int warp = tid >> 5;
    const int wm = warp >> 2;   // 0..1  (64 rows each)
    const int wn = warp & 3;    // 0..3  (32 cols each)
    const int bm = blockIdx.y;  // 0..7
    const int bn = blockIdx.x;  // 0..48

    float acc[4][4][4];
    #pragma unroll
    for (int i = 0; i < 4; i++)
        #pragma unroll
        for (int j = 0; j < 4; j++)
            #pragma unroll
            for (int k = 0; k < 4; k++) acc[i][j][k] = 0.f;

    const int c0row = tid >> 2,          c0k = tid & 3;
    const int c1row = (tid + 256) >> 2;

    auto issue_load = [&](int st, int kb) {
        __nv_bfloat16* sA = gsm + st * STAGE_E;
        __nv_bfloat16* sB = sA + AB_HALF;
        cp_async16((uint32_t)__cvta_generic_to_shared(&sA[c0row * SSTR + c0k * 8]),
                   A + (size_t)(bm * 128 + c0row) * D_DIM + kb * 32 + c0k * 8);
        cp_async16((uint32_t)__cvta_generic_to_shared(&sA[c1row * SSTR + c0k * 8]),
                   A + (size_t)(bm * 128 + c1row) * D_DIM + kb * 32 + c0k * 8);
        cp_async16((uint32_t)__cvta_generic_to_shared(&sB[c0row * SSTR + c0k * 8]),
                   Bm + (size_t)(bn * 128 + c0row) * D_DIM + kb * 32 + c0k * 8);
        cp_async16((uint32_t)__cvta_generic_to_shared(&sB[c1row * SSTR + c0k * 8]),
                   Bm + (size_t)(bn * 128 + c1row) * D_DIM + kb * 32 + c0k * 8);
        asm volatile("cp.async.commit_group;\n");
    };

    // prologue: 3-chunk lead
    issue_load(0, 0);
    issue_load(1, 1);
    issue_load(2, 2);

    const int a_row  = lane & 15;
    const int a_koff = (lane >> 4) * 8;
    const int b_n    = ((lane >> 4) & 1) * 8 + (lane & 7);
    const int b_k    = ((lane >> 3) & 1) * 8;

    for (int kb = 0; kb < 32; kb++) {
        // wait for chunk kb; pending beyond it = min(2, 31-kb)
        const int rem = 31 - kb;
        if (rem >= 2)      asm volatile("cp.async.wait_group 2;\n");
        else if (rem == 1) asm volatile("cp.async.wait_group 1;\n");
        else               asm volatile("cp.async.wait_group 0;\n");
        __syncthreads();   // data visible + all warps done with stage (kb-1)%4

        if (kb + 3 < 32) issue_load((kb + 3) & 3, kb + 3);

        const __nv_bfloat16* sA = gsm + (kb & 3) * STAGE_E;
        const __nv_bfloat16* sB = sA + AB_HALF;
        #pragma unroll
        for (int ks = 0; ks < 2; ks++) {
            uint32_t a[4][4], b[4][2];
            #pragma unroll
            for (int mt = 0; mt < 4; mt++) {
                int row = wm * 64 + mt * 16 + a_row;
                ldsm_x4(a[mt], (uint32_t)__cvta_generic_to_shared(
                    &sA[row * SSTR + ks * 16 + a_koff]));
            }
            #pragma unroll
            for (int bp = 0; bp < 2; bp++) {
                uint32_t r[4];
                int row = wn * 32 + bp * 16 + b_n;
                ldsm_x4(r, (uint32_t)__cvta_generic_to_shared(
                    &sB[row * SSTR + ks * 16 + b_k]));
                b[2 * bp][0] = r[0]; b[2 * bp][1] = r[1];
                b[2 * bp + 1][0] = r[2]; b[2 * bp + 1][1] = r[3];
            }
            #pragma unroll
            for (int mt = 0; mt < 4; mt++)
                #pragma unroll
                for (int nt = 0; nt < 4; nt++)
                    mma16816(acc[mt][nt], a[mt], b[nt]);
        }
    }

    // epilogue: write f32 sims
    #pragma unroll
    for (int mt = 0; mt < 4; mt++) {
        const int m = bm * 128 + wm * 64 + mt * 16 + (lane >> 2);
        #pragma unroll
        for (int nt = 0; nt < 4; nt++) {
            const int n = bn * 128 + wn * 32 + nt * 8 + (lane & 3) * 2;
            *reinterpret_cast<float2*>(&g_sim[(size_t)m * NCOLS + n]) =
                make_float2(acc[mt][nt][0], acc[mt][nt][1]);
            *reinterpret_cast<float2*>(&g_sim[(size_t)(m + 8) * NCOLS + n]) =
                make_float2(acc[mt][nt][2], acc[mt][nt][3]);
        }
    }
}

// ---------------- kernel 3: dual masked softmax over p + combine ----------------
__global__ __launch_bounds__(256) void softmax_kernel(
    const float* __restrict__ cpred,
    const int* __restrict__ tmask,
    const int* __restrict__ vmask,
    const int* __restrict__ cmask,
    float* __restrict__ out, int wmm, int wcp)
{
    const int gw   = (int)((blockIdx.x * blockDim.x + threadIdx.x) >> 5);
    const int lane = threadIdx.x & 31;
    const int bq = gw >> 5;
    const int c  = gw & 31;
    const size_t base = (size_t)bq * NCOLS + c * P_DIM;
    const float NEG = __int_as_float(0xff800000);

    const bool tm = tmask[bq] != 0;
    float x[7], y[7];
    bool m1[7], m2[7];
    float mx = NEG, my = NEG;
    #pragma unroll
    for (int i = 0; i < 7; i++) {
        const int p = lane + 32 * i;
        if (p < P_DIM) {
            const bool vm = vmask[c * P_DIM + p] != 0;
            m1[i] = tm && vm;
            m2[i] = cmask[base + p] != 0;
            x[i] = m1[i] ? g_sim[base + p] : NEG;
            y[i] = m2[i] ? cpred[base + p] : NEG;
        } else { x[i] = NEG; y[i] = NEG; m1[i] = false; m2[i] = false; }
        mx = fmaxf(mx, x[i]); my = fmaxf(my, y[i]);
    }
    #pragma unroll
    for (int o = 16; o; o >>= 1) {
        mx = fmaxf(mx, __shfl_xor_sync(0xffffffffu, mx, o));
        my = fmaxf(my, __shfl_xor_sync(0xffffffffu, my, o));
    }
    float ex[7], ey[7], sx = 0.f, sy = 0.f;
    #pragma unroll
    for (int i = 0; i < 7; i++) {
        ex[i] = __expf(x[i] - mx);
        ey[i] = __expf(y[i] - my);
        if (lane + 32 * i < P_DIM) { sx += ex[i]; sy += ey[i]; }
    }
    #pragma unroll
    for (int o = 16; o; o >>= 1) {
        sx += __shfl_xor_sync(0xffffffffu, sx, o);
        sy += __shfl_xor_sync(0xffffffffu, sy, o);
    }
    const float rsx = 1.f / sx, rsy = 1.f / sy;
    #pragma unroll
    for (int i = 0; i < 7; i++) {
        const int p = lane + 32 * i;
        if (p < P_DIM) {
            const float mmv = ex[i] * rsx;
            const float cpv = ey[i] * rsy;
            out[base + p] = (m1[i] && m2[i]) ? 0.5f * (mmv + cpv) : 0.f;
            if (wmm) out[(size_t)N4 + base + p] = mmv;
            if (wcp) out[2 * (size_t)N4 + base + p] = cpv;
        }
    }
}

// ---------------- launch ----------------
extern "C" void kernel_launch(void* const* d_in, const int* in_sizes, int n_in,
                              void* d_out, int out_size)
{
    const float* visual_feat   = (const float*)d_in[0];
    const int*   visual_mask   = (const int*)d_in[1];
    const float* textual_feat  = (const float*)d_in[2];
    const int*   textual_mask  = (const int*)d_in[3];
    const float* concepts_pred = (const float*)d_in[4];
    const int*   concepts_mask = (const int*)d_in[5];
    float* out = (float*)d_out;

    const int wmm = (out_size >= 2 * N4) ? 1 : 0;
    const int wcp = (out_size >= 3 * N4) ? 1 : 0;

    normalize_kernel<<<(MROWS + NCOLS) / 8, 256>>>(textual_feat, visual_feat);

    cudaFuncSetAttribute(gemm_kernel,
                         cudaFuncAttributeMaxDynamicSharedMemorySize, GM_SMEM);
    dim3 ggrid(NCOLS / 128, MROWS / 128);   // (49, 8)
    gemm_kernel<<<ggrid, 256, GM_SMEM>>>();

    softmax_kernel<<<4096, 256>>>(concepts_pred, textual_mask, visual_mask,
                                  concepts_mask, out, wmm, wcp);
}

// round 9
// speedup vs baseline: 1.0738x; 1.0738x over previous
#include <cuda_runtime.h>
#include <cuda_bf16.h>
#include <cstdint>
#include <math.h>

#define B_DIM 32
#define Q_DIM 32
#define P_DIM 196
#define D_DIM 1024
#define MROWS (B_DIM*Q_DIM)        // 1024
#define NCOLS (B_DIM*P_DIM)        // 6272
#define N4    (MROWS*NCOLS)

// ---------------- scratch ----------------
__device__ __nv_bfloat16 g_tn[MROWS * D_DIM];
__device__ __nv_bfloat16 g_vn[NCOLS * D_DIM];
__device__ float         g_sim[(size_t)MROWS * NCOLS];

// ---------------- kernel 1: warp-per-row L2 normalize + f32->bf16 ----------------
__global__ __launch_bounds__(256) void normalize_kernel(const float* __restrict__ tf,
                                                        const float* __restrict__ vf)
{
    const int w = blockIdx.x * 8 + (threadIdx.x >> 5);
    const int lane = threadIdx.x & 31;
    const float* in;
    __nv_bfloat16* out;
    int row;
    if (w < MROWS) { in = tf; out = g_tn; row = w; }
    else           { in = vf; out = g_vn; row = w - MROWS; }

    const float4* src = reinterpret_cast<const float4*>(in + (size_t)row * D_DIM);
    float4 v[8];
    float ss = 0.f;
    #pragma unroll
    for (int i = 0; i < 8; i++) {
        v[i] = src[i * 32 + lane];
        ss += v[i].x*v[i].x + v[i].y*v[i].y + v[i].z*v[i].z + v[i].w*v[i].w;
    }
    #pragma unroll
    for (int o = 16; o; o >>= 1) ss += __shfl_xor_sync(0xffffffffu, ss, o);
    const float s = 1.0f / fmaxf(sqrtf(ss), 1e-8f);

    uint2* dst = reinterpret_cast<uint2*>(out + (size_t)row * D_DIM);
    #pragma unroll
    for (int i = 0; i < 8; i++) {
        __nv_bfloat162 h0 = __floats2bfloat162_rn(v[i].x * s, v[i].y * s);
        __nv_bfloat162 h1 = __floats2bfloat162_rn(v[i].z * s, v[i].w * s);
        uint2 u;
        u.x = *reinterpret_cast<uint32_t*>(&h0);
        u.y = *reinterpret_cast<uint32_t*>(&h1);
        dst[i * 32 + lane] = u;
    }
}

// ---------------- kernel 2: bf16 tensor-core GEMM  C[M,N] = A[M,K] * B[N,K]^T ----------------
__device__ __forceinline__ void cp_async16(uint32_t dst, const void* src) {
    asm volatile("cp.async.cg.shared.global [%0], [%1], 16;\n" :: "r"(dst), "l"(src));
}
__device__ __forceinline__ void ldsm_x4(uint32_t* r, uint32_t addr) {
    asm volatile("ldmatrix.sync.aligned.m8n8.x4.shared.b16 {%0,%1,%2,%3}, [%4];\n"
                 : "=r"(r[0]), "=r"(r[1]), "=r"(r[2]), "=r"(r[3]) : "r"(addr));
}
__device__ __forceinline__ void mma16816(float* c, const uint32_t* a, const uint32_t* b) {
    asm volatile("mma.sync.aligned.m16n8k16.row.col.f32.bf16.bf16.f32 "
                 "{%0,%1,%2,%3}, {%4,%5,%6,%7}, {%8,%9}, {%0,%1,%2,%3};\n"
                 : "+f"(c[0]), "+f"(c[1]), "+f"(c[2]), "+f"(c[3])
                 : "r"(a[0]), "r"(a[1]), "r"(a[2]), "r"(a[3]), "r"(b[0]), "r"(b[1]));
}

// K-chunk = 64 bf16; padded row stride 72 elems (144B -> 9x16B chunks, conflict-free)
#define CK      64
#define SSTR    72
#define HALF_E  (128 * SSTR)              // elems per A (or B) half-stage = 9216
#define STAGE_E (2 * HALF_E)              // 18432 elems = 36864 B
#define STAGES  3
#define GM_SMEM (STAGES * STAGE_E * 2)    // 110592 B

extern __shared__ __nv_bfloat16 gsm[];

__global__ __launch_bounds__(256, 2) void gemm_kernel()
{
    const __nv_bfloat16* __restrict__ A  = g_tn;
    const __nv_bfloat16* __restrict__ Bm = g_vn;

    const int tid  = threadIdx.x;
    const int lane = tid & 31;
    const int warp = tid >> 5;
    const int wm = warp >> 2;   // 0..1  (64 rows each)
    const int wn = warp & 3;    // 0..3  (32 cols each)
    const int bm = blockIdx.y;  // 0..7
    const int bn = blockIdx.x;  // 0..48

    float acc[4][4][4];
    #pragma unroll
    for (int i = 0; i < 4; i++)
        #pragma unroll
        for (int j = 0; j < 4; j++)
            #pragma unroll
            for (int k = 0; k < 4; k++) acc[i][j][k] = 0.f;

    // cp.async map: 2048 16B-chunks per stage (A 1024 + B 1024), 8 per thread
    const int ldr = tid >> 3;        // 0..31 base row group? (tid/8)
    const int ldc = tid & 7;         // chunk col 0..7
    auto issue_load = [&](int st, int kb) {
        __nv_bfloat16* sA = gsm + st * STAGE_E;
        __nv_bfloat16* sB = sA + HALF_E;
        #pragma unroll
        for (int i = 0; i < 4; i++) {
            const int r = ldr + i * 32;  // 0..127
            cp_async16((uint32_t)__cvta_generic_to_shared(&sA[r * SSTR + ldc * 8]),
                       A + (size_t)(bm * 128 + r) * D_DIM + kb * CK + ldc * 8);
        }
        #pragma unroll
        for (int i = 0; i < 4; i++) {
            const int r = ldr + i * 32;
            cp_async16((uint32_t)__cvta_generic_to_shared(&sB[r * SSTR + ldc * 8]),
                       Bm + (size_t)(bn * 128 + r) * D_DIM + kb * CK + ldc * 8);
        }
        asm volatile("cp.async.commit_group;\n");
    };

    // prologue: 2-chunk lead
    issue_load(0, 0);
    issue_load(1, 1);

    const int a_row  = lane & 15;
    const int a_koff = (lane >> 4) * 8;
    const int b_n    = ((lane >> 4) & 1) * 8 + (lane & 7);
    const int b_k    = ((lane >> 3) & 1) * 8;

    #define NKB (D_DIM / CK)   // 16
    for (int kb = 0; kb < NKB; kb++) {
        if (kb < NKB - 1) asm volatile("cp.async.wait_group 1;\n");
        else              asm volatile("cp.async.wait_group 0;\n");
        __syncthreads();   // chunk kb visible; all warps done with stage (kb+2)%3

        if (kb + 2 < NKB) issue_load((kb + 2) % STAGES, kb + 2);

        const __nv_bfloat16* sA = gsm + (kb % STAGES) * STAGE_E;
        const __nv_bfloat16* sB = sA + HALF_E;
        #pragma unroll
        for (int ks = 0; ks < 4; ks++) {
            uint32_t a[4][4], b[4][2];
            #pragma unroll
            for (int mt = 0; mt < 4; mt++) {
                int row = wm * 64 + mt * 16 + a_row;
                ldsm_x4(a[mt], (uint32_t)__cvta_generic_to_shared(
                    &sA[row * SSTR + ks * 16 + a_koff]));
            }
            #pragma unroll
            for (int bp = 0; bp < 2; bp++) {
                uint32_t r[4];
                int row = wn * 32 + bp * 16 + b_n;
                ldsm_x4(r, (uint32_t)__cvta_generic_to_shared(
                    &sB[row * SSTR + ks * 16 + b_k]));
                b[2 * bp][0] = r[0]; b[2 * bp][1] = r[1];
                b[2 * bp + 1][0] = r[2]; b[2 * bp + 1][1] = r[3];
            }
            #pragma unroll
            for (int mt = 0; mt < 4; mt++)
                #pragma unroll
                for (int nt = 0; nt < 4; nt++)
                    mma16816(acc[mt][nt], a[mt], b[nt]);
        }
    }

    // epilogue: write f32 sims
    #pragma unroll
    for (int mt = 0; mt < 4; mt++) {
        const int m = bm * 128 + wm * 64 + mt * 16 + (lane >> 2);
        #pragma unroll
        for (int nt = 0; nt < 4; nt++) {
            const int n = bn * 128 + wn * 32 + nt * 8 + (lane & 3) * 2;
            *reinterpret_cast<float2*>(&g_sim[(size_t)m * NCOLS + n]) =
                make_float2(acc[mt][nt][0], acc[mt][nt][1]);
            *reinterpret_cast<float2*>(&g_sim[(size_t)(m + 8) * NCOLS + n]) =
                make_float2(acc[mt][nt][2], acc[mt][nt][3]);
        }
    }
}

// ---------------- kernel 3: dual masked softmax over p + combine ----------------
__global__ __launch_bounds__(256) void softmax_kernel(
    const float* __restrict__ cpred,
    const int* __restrict__ tmask,
    const int* __restrict__ vmask,
    const int* __restrict__ cmask,
    float* __restrict__ out, int wmm, int wcp)
{
    const int gw   = (int)((blockIdx.x * blockDim.x + threadIdx.x) >> 5);
    const int lane = threadIdx.x & 31;
    const int bq = gw >> 5;
    const int c  = gw & 31;
    const size_t base = (size_t)bq * NCOLS + c * P_DIM;
    const float NEG = __int_as_float(0xff800000);

    const bool tm = tmask[bq] != 0;
    float x[7], y[7];
    bool m1[7], m2[7];
    float mx = NEG, my = NEG;
    #pragma unroll
    for (int i = 0; i < 7; i++) {
        const int p = lane + 32 * i;
        if (p < P_DIM) {
            const bool vm = vmask[c * P_DIM + p] != 0;
            m1[i] = tm && vm;
            m2[i] = cmask[base + p] != 0;
            x[i] = m1[i] ? g_sim[base + p] : NEG;
            y[i] = m2[i] ? cpred[base + p] : NEG;
        } else { x[i] = NEG; y[i] = NEG; m1[i] = false; m2[i] = false; }
        mx = fmaxf(mx, x[i]); my = fmaxf(my, y[i]);
    }
    #pragma unroll
    for (int o = 16; o; o >>= 1) {
        mx = fmaxf(mx, __shfl_xor_sync(0xffffffffu, mx, o));
        my = fmaxf(my, __shfl_xor_sync(0xffffffffu, my, o));
    }
    float ex[7], ey[7], sx = 0.f, sy = 0.f;
    #pragma unroll
    for (int i = 0; i < 7; i++) {
        ex[i] = __expf(x[i] - mx);
        ey[i] = __expf(y[i] - my);
        if (lane + 32 * i < P_DIM) { sx += ex[i]; sy += ey[i]; }
    }
    #pragma unroll
    for (int o = 16; o; o >>= 1) {
        sx += __shfl_xor_sync(0xffffffffu, sx, o);
        sy += __shfl_xor_sync(0xffffffffu, sy, o);
    }
    const float rsx = 1.f / sx, rsy = 1.f / sy;
    #pragma unroll
    for (int i = 0; i < 7; i++) {
        const int p = lane + 32 * i;
        if (p < P_DIM) {
            const float mmv = ex[i] * rsx;
            const float cpv = ey[i] * rsy;
            out[base + p] = (m1[i] && m2[i]) ? 0.5f * (mmv + cpv) : 0.f;
            if (wmm) out[(size_t)N4 + base + p] = mmv;
            if (wcp) out[2 * (size_t)N4 + base + p] = cpv;
        }
    }
}

// ---------------- launch ----------------
extern "C" void kernel_launch(void* const* d_in, const int* in_sizes, int n_in,
                              void* d_out, int out_size)
{
    const float* visual_feat   = (const float*)d_in[0];
    const int*   visual_mask   = (const int*)d_in[1];
    const float* textual_feat  = (const float*)d_in[2];
    const int*   textual_mask  = (const int*)d_in[3];
    const float* concepts_pred = (const float*)d_in[4];
    const int*   concepts_mask = (const int*)d_in[5];
    float* out = (float*)d_out;

    const int wmm = (out_size >= 2 * N4) ? 1 : 0;
    const int wcp = (out_size >= 3 * N4) ? 1 : 0;

    normalize_kernel<<<(MROWS + NCOLS) / 8, 256>>>(textual_feat, visual_feat);

    cudaFuncSetAttribute(gemm_kernel,
                         cudaFuncAttributeMaxDynamicSharedMemorySize, GM_SMEM);
    dim3 ggrid(NCOLS / 128, MROWS / 128);   // (49, 8)
    gemm_kernel<<<ggrid, 256, GM_SMEM>>>();

    softmax_kernel<<<4096, 256>>>(concepts_pred, textual_mask, visual_mask,
                                  concepts_mask, out, wmm, wcp);
}